// round 1
// baseline (speedup 1.0000x reference)
#include <cuda_runtime.h>
#include <math.h>

#define NB 8
#define NT 2048
#define NC 1024
#define NH 128
#define NBT (NB*NT)

// Scratch for projected Q/K/V: [B*T, H] each (8 MB apiece). Static device
// globals — no runtime allocation.
__device__ float g_Q[NBT*NH];
__device__ float g_K[NBT*NH];
__device__ float g_V[NBT*NH];

// ---------------------------------------------------------------------------
// QKV projection: out[m][n] = sum_k x[m][k] * W[n][k]
// M = 16384, N = 128, K = 1024. blockIdx.y in {0,1,2} selects Wq/Wk/Wv.
// Classic 128x128 block, BK=8, 256 threads, 8x8 microtile per thread.
// ---------------------------------------------------------------------------
__global__ __launch_bounds__(256, 2)
void qkv_proj_kernel(const float* __restrict__ x,
                     const float* __restrict__ Wq,
                     const float* __restrict__ Wk,
                     const float* __restrict__ Wv) {
    __shared__ float As[8][128];   // As[k][m]
    __shared__ float Bs[8][128];   // Bs[k][n]

    const float* __restrict__ W = (blockIdx.y == 0) ? Wq : (blockIdx.y == 1) ? Wk : Wv;
    float* out = (blockIdx.y == 0) ? g_Q : (blockIdx.y == 1) ? g_K : g_V;

    const int tid  = threadIdx.x;
    const int m0   = blockIdx.x * 128;
    const int lrow = tid >> 1;          // 0..127 (row of A tile / row of W)
    const int lk   = (tid & 1) * 4;     // 0 or 4
    const int trow = (tid >> 4) * 8;    // microtile row base
    const int tcol = (tid & 15) * 8;    // microtile col base

    float acc[8][8];
    #pragma unroll
    for (int i = 0; i < 8; i++)
        #pragma unroll
        for (int j = 0; j < 8; j++) acc[i][j] = 0.f;

    const float* xg = x + (size_t)(m0 + lrow) * NC + lk;
    const float* wg = W + (size_t)lrow * NC + lk;

    for (int k0 = 0; k0 < NC; k0 += 8) {
        float4 av = *(const float4*)(xg + k0);
        float4 bv = *(const float4*)(wg + k0);
        __syncthreads();
        As[lk+0][lrow] = av.x; As[lk+1][lrow] = av.y;
        As[lk+2][lrow] = av.z; As[lk+3][lrow] = av.w;
        Bs[lk+0][lrow] = bv.x; Bs[lk+1][lrow] = bv.y;
        Bs[lk+2][lrow] = bv.z; Bs[lk+3][lrow] = bv.w;
        __syncthreads();
        #pragma unroll
        for (int k = 0; k < 8; k++) {
            float4 a0 = *(const float4*)&As[k][trow];
            float4 a1 = *(const float4*)&As[k][trow + 4];
            float4 b0 = *(const float4*)&Bs[k][tcol];
            float4 b1 = *(const float4*)&Bs[k][tcol + 4];
            float a[8] = {a0.x, a0.y, a0.z, a0.w, a1.x, a1.y, a1.z, a1.w};
            float b[8] = {b0.x, b0.y, b0.z, b0.w, b1.x, b1.y, b1.z, b1.w};
            #pragma unroll
            for (int i = 0; i < 8; i++)
                #pragma unroll
                for (int j = 0; j < 8; j++)
                    acc[i][j] += a[i] * b[j];
        }
    }

    #pragma unroll
    for (int i = 0; i < 8; i++) {
        float4 o0 = make_float4(acc[i][0], acc[i][1], acc[i][2], acc[i][3]);
        float4 o1 = make_float4(acc[i][4], acc[i][5], acc[i][6], acc[i][7]);
        *(float4*)&out[(size_t)(m0 + trow + i) * NH + tcol]     = o0;
        *(float4*)&out[(size_t)(m0 + trow + i) * NH + tcol + 4] = o1;
    }
}

// ---------------------------------------------------------------------------
// Flash attention: one CTA per (batch, 64-row q tile).
// K/V processed in 64-row tiles with online softmax.
// Q,K stored d-major (transposed, stride 68) in smem for conflict-free
// reduction reads; P stored transposed for the P@V pass.
// ---------------------------------------------------------------------------
#define PSTR 68

__global__ __launch_bounds__(256, 1)
void attn_kernel(float* __restrict__ out) {
    extern __shared__ float sm[];
    float* Qt  = sm;                   // [128][PSTR]  Qt[d][i]
    float* Kt  = Qt + 128 * PSTR;      // [128][PSTR]  Kt[d][j]
    float* Vs  = Kt + 128 * PSTR;      // [64][128]    Vs[j][h]
    float* Pt  = Vs + 64 * NH;         // [64][PSTR]   Pt[j][i]
    float* m_s = Pt + 64 * PSTR;       // [64]
    float* l_s = m_s + 64;             // [64]

    const int b     = blockIdx.y;
    const int qtile = (int)gridDim.x - 1 - (int)blockIdx.x;  // longest first
    const int q0    = qtile * 64;
    const int tid   = threadIdx.x;
    const int l16   = tid & 15;
    const int ti    = (tid >> 4) * 4;  // S/O row base (4 rows)
    const int tj    = l16 * 4;         // S col base   (4 cols)
    const int tcol  = l16 * 8;         // O col base   (8 cols)

    // Load Q tile transposed
    const float* Qg = g_Q + ((size_t)b * NT + q0) * NH;
    #pragma unroll
    for (int it = 0; it < 8; it++) {
        int i  = tid + it * 256;
        int r  = i >> 5;
        int d4 = (i & 31) * 4;
        float4 v = *(const float4*)&Qg[r * NH + d4];
        Qt[(d4+0)*PSTR + r] = v.x;
        Qt[(d4+1)*PSTR + r] = v.y;
        Qt[(d4+2)*PSTR + r] = v.z;
        Qt[(d4+3)*PSTR + r] = v.w;
    }
    if (tid < 64) { m_s[tid] = -INFINITY; l_s[tid] = 0.f; }

    float acc[4][8];
    #pragma unroll
    for (int i = 0; i < 4; i++)
        #pragma unroll
        for (int j = 0; j < 8; j++) acc[i][j] = 0.f;

    const float scale = 0.08838834764831845f;  // 1/sqrt(128)

    for (int kt = 0; kt <= qtile; kt++) {
        const int k0 = kt * 64;
        __syncthreads();   // previous iter's Kt/Vs/Pt reads done
        const float* Kg = g_K + ((size_t)b * NT + k0) * NH;
        const float* Vg = g_V + ((size_t)b * NT + k0) * NH;
        #pragma unroll
        for (int it = 0; it < 8; it++) {
            int i  = tid + it * 256;
            int r  = i >> 5;
            int d4 = (i & 31) * 4;
            float4 v = *(const float4*)&Kg[r * NH + d4];
            Kt[(d4+0)*PSTR + r] = v.x;
            Kt[(d4+1)*PSTR + r] = v.y;
            Kt[(d4+2)*PSTR + r] = v.z;
            Kt[(d4+3)*PSTR + r] = v.w;
            float4 w = *(const float4*)&Vg[r * NH + d4];
            *(float4*)&Vs[r * NH + d4] = w;
        }
        __syncthreads();

        // ---- S = Q @ K^T (4x4 per thread over d=128) ----
        float s[4][4];
        #pragma unroll
        for (int i = 0; i < 4; i++)
            #pragma unroll
            for (int j = 0; j < 4; j++) s[i][j] = 0.f;

        #pragma unroll 8
        for (int d = 0; d < 128; d++) {
            float4 aq = *(const float4*)&Qt[d * PSTR + ti];
            float4 bk = *(const float4*)&Kt[d * PSTR + tj];
            float av[4] = {aq.x, aq.y, aq.z, aq.w};
            float bv[4] = {bk.x, bk.y, bk.z, bk.w};
            #pragma unroll
            for (int i = 0; i < 4; i++)
                #pragma unroll
                for (int j = 0; j < 4; j++)
                    s[i][j] += av[i] * bv[j];
        }

        // ---- online softmax per row (16-lane shfl reductions) ----
        const bool diag = (kt == qtile);
        float alpha[4];
        #pragma unroll
        for (int ii = 0; ii < 4; ii++) {
            float rmax = -INFINITY;
            #pragma unroll
            for (int jj = 0; jj < 4; jj++) {
                float sv = s[ii][jj] * scale;
                if (diag && (tj + jj > ti + ii)) sv = -INFINITY;
                s[ii][jj] = sv;
                rmax = fmaxf(rmax, sv);
            }
            #pragma unroll
            for (int off = 8; off > 0; off >>= 1)
                rmax = fmaxf(rmax, __shfl_xor_sync(0xffffffffu, rmax, off, 16));
            float mold = m_s[ti + ii];
            float mnew = fmaxf(mold, rmax);
            float a_   = (mold == -INFINITY) ? 0.f : __expf(mold - mnew);
            alpha[ii] = a_;
            float rsum = 0.f;
            #pragma unroll
            for (int jj = 0; jj < 4; jj++) {
                float p = __expf(s[ii][jj] - mnew);
                s[ii][jj] = p;
                rsum += p;
            }
            #pragma unroll
            for (int off = 8; off > 0; off >>= 1)
                rsum += __shfl_xor_sync(0xffffffffu, rsum, off, 16);
            if (l16 == 0) {
                m_s[ti + ii] = mnew;
                l_s[ti + ii] = l_s[ti + ii] * a_ + rsum;
            }
        }

        // P to smem, transposed
        #pragma unroll
        for (int ii = 0; ii < 4; ii++)
            #pragma unroll
            for (int jj = 0; jj < 4; jj++)
                Pt[(tj + jj) * PSTR + (ti + ii)] = s[ii][jj];
        __syncthreads();

        // rescale O, then O += P @ V
        #pragma unroll
        for (int ii = 0; ii < 4; ii++)
            #pragma unroll
            for (int cc = 0; cc < 8; cc++)
                acc[ii][cc] *= alpha[ii];

        #pragma unroll 4
        for (int j = 0; j < 64; j++) {
            float4 p4 = *(const float4*)&Pt[j * PSTR + ti];
            float4 v0 = *(const float4*)&Vs[j * NH + tcol];
            float4 v1 = *(const float4*)&Vs[j * NH + tcol + 4];
            float pv[4] = {p4.x, p4.y, p4.z, p4.w};
            float vv[8] = {v0.x, v0.y, v0.z, v0.w, v1.x, v1.y, v1.z, v1.w};
            #pragma unroll
            for (int ii = 0; ii < 4; ii++)
                #pragma unroll
                for (int cc = 0; cc < 8; cc++)
                    acc[ii][cc] += pv[ii] * vv[cc];
        }
    }

    __syncthreads();
    float* Og = out + ((size_t)b * NT + q0) * NH;
    #pragma unroll
    for (int ii = 0; ii < 4; ii++) {
        float inv = 1.f / l_s[ti + ii];
        float4 o0 = make_float4(acc[ii][0]*inv, acc[ii][1]*inv, acc[ii][2]*inv, acc[ii][3]*inv);
        float4 o1 = make_float4(acc[ii][4]*inv, acc[ii][5]*inv, acc[ii][6]*inv, acc[ii][7]*inv);
        *(float4*)&Og[(ti + ii) * NH + tcol]     = o0;
        *(float4*)&Og[(ti + ii) * NH + tcol + 4] = o1;
    }
}

// ---------------------------------------------------------------------------
extern "C" void kernel_launch(void* const* d_in, const int* in_sizes, int n_in,
                              void* d_out, int out_size) {
    const float* x  = (const float*)d_in[0];
    const float* Wq = (const float*)d_in[1];
    const float* Wk = (const float*)d_in[2];
    const float* Wv = (const float*)d_in[3];
    float* out = (float*)d_out;

    qkv_proj_kernel<<<dim3(NBT / 128, 3), 256>>>(x, Wq, Wk, Wv);

    const int smem_bytes = (128 * PSTR * 2 + 64 * NH + 64 * PSTR + 128) * (int)sizeof(float);
    cudaFuncSetAttribute(attn_kernel,
                         cudaFuncAttributeMaxDynamicSharedMemorySize, smem_bytes);
    attn_kernel<<<dim3(NT / 64, NB), 256, smem_bytes>>>(out);
}